// round 2
// baseline (speedup 1.0000x reference)
#include <cuda_runtime.h>
#include <math.h>

#define SEQ   2048
#define HID   4096
#define NQH   32
#define NKVH  8
#define HD    128
#define KVD   1024
#define QKVN  6144   // 4096 + 2*1024

// Scratch (device globals — no allocation allowed)
__device__ float g_qkv[(size_t)SEQ * QKVN];                 // 50 MB
__device__ float g_scores[(size_t)NQH * SEQ * SEQ];         // 512 MB
__device__ float g_attn[(size_t)SEQ * HID];                 // 32 MB

// ---------------------------------------------------------------------------
// Generic NN SGEMM with bias: C[M,N] = A[M,K] @ B[K,N] (+ bias)
// 128x128 block, BK=8, 256 threads, 8x8 per thread.
// Requires M%128==0, N%128==0, K%8==0, all ld's %4==0.
// ---------------------------------------------------------------------------
__global__ __launch_bounds__(256) void sgemm_nn_bias(
    int M, int N, int K,
    const float* __restrict__ A, int lda,
    const float* __restrict__ B, int ldb,
    const float* __restrict__ bias,
    float* __restrict__ C, int ldc)
{
    __shared__ float As[8][128];
    __shared__ float Bs[8][128];

    const int bx = blockIdx.x, by = blockIdx.y;
    const int tid = threadIdx.x;
    const int trow = tid >> 4;      // 0..15
    const int tcol = tid & 15;      // 0..15

    const float* Ab = A + (size_t)by * 128 * lda;
    const float* Bb = B + (size_t)bx * 128;

    const int aRow = tid >> 1;            // 0..127
    const int aCol = (tid & 1) * 4;       // 0 or 4
    const int bRow = tid >> 5;            // 0..7
    const int bCol = (tid & 31) * 4;      // 0..124

    float acc[8][8];
#pragma unroll
    for (int i = 0; i < 8; i++)
#pragma unroll
        for (int j = 0; j < 8; j++) acc[i][j] = 0.f;

    for (int k0 = 0; k0 < K; k0 += 8) {
        float4 av = *(const float4*)(Ab + (size_t)aRow * lda + k0 + aCol);
        As[aCol + 0][aRow] = av.x;
        As[aCol + 1][aRow] = av.y;
        As[aCol + 2][aRow] = av.z;
        As[aCol + 3][aRow] = av.w;
        *(float4*)&Bs[bRow][bCol] =
            *(const float4*)(Bb + (size_t)(k0 + bRow) * ldb + bCol);
        __syncthreads();
#pragma unroll
        for (int kk = 0; kk < 8; kk++) {
            float ar[8], br[8];
#pragma unroll
            for (int i = 0; i < 8; i++) ar[i] = As[kk][trow * 8 + i];
#pragma unroll
            for (int j = 0; j < 8; j++) br[j] = Bs[kk][tcol * 8 + j];
#pragma unroll
            for (int i = 0; i < 8; i++)
#pragma unroll
                for (int j = 0; j < 8; j++) acc[i][j] += ar[i] * br[j];
        }
        __syncthreads();
    }

#pragma unroll
    for (int i = 0; i < 8; i++) {
        const int row = by * 128 + trow * 8 + i;
#pragma unroll
        for (int j = 0; j < 8; j += 4) {
            const int col = bx * 128 + tcol * 8 + j;
            float4 v;
            v.x = acc[i][j];     v.y = acc[i][j + 1];
            v.z = acc[i][j + 2]; v.w = acc[i][j + 3];
            if (bias) {
                v.x += bias[col];     v.y += bias[col + 1];
                v.z += bias[col + 2]; v.w += bias[col + 3];
            }
            *(float4*)(C + (size_t)row * ldc + col) = v;
        }
    }
}

// ---------------------------------------------------------------------------
// RoPE on Q (32 heads) and K (8 heads) in place inside g_qkv.
// One thread per (s, head, freq-pair). Double-precision angle for safety.
// ---------------------------------------------------------------------------
__global__ void rope_kernel(const int* __restrict__ positions)
{
    const int total = SEQ * 40 * 64;
    int idx = blockIdx.x * blockDim.x + threadIdx.x;
    if (idx >= total) return;
    const int i    = idx & 63;          // frequency index 0..63
    const int head = (idx >> 6) % 40;   // 0..31 = Q heads, 32..39 = K heads
    const int s    = idx / (40 * 64);

    float* base = g_qkv + (size_t)s * QKVN +
                  (head < 32 ? head * HD : HID + (head - 32) * HD);

    const double pos = (double)positions[s];
    // inv_freq = 10000^(-i/64)
    const double inv_freq = exp(-(double)i * (9.210340371976184 / 64.0));
    const double a = pos * inv_freq;
    const float c  = (float)cos(a);
    const float sn = (float)sin(a);

    const float x1 = base[i];
    const float x2 = base[i + 64];
    base[i]      = x1 * c - x2 * sn;
    base[i + 64] = x2 * c + x1 * sn;
}

// ---------------------------------------------------------------------------
// Scores: per head h, S[s,t] = scale * (q_s . k_t)  (NT GEMM, K=128).
// Blocks fully above the causal diagonal are skipped entirely (softmax
// only reads t<=s and zero-fills t>s).
// grid: (16, 16, 32)
// ---------------------------------------------------------------------------
__global__ __launch_bounds__(256) void scores_nt(float scale)
{
    const int h  = blockIdx.z;
    const int s0 = blockIdx.y * 128;
    const int t0 = blockIdx.x * 128;
    if (t0 > s0 + 127) return;   // fully masked block — never read downstream

    float* Cb = g_scores + (size_t)h * SEQ * SEQ;
    const float* Qb = g_qkv + (size_t)s0 * QKVN + h * HD;
    const float* Kb = g_qkv + (size_t)t0 * QKVN + HID + (h >> 2) * HD;

    __shared__ float Qs[8][128];
    __shared__ float Ks[8][128];

    const int tid  = threadIdx.x;
    const int trow = tid >> 4, tcol = tid & 15;
    const int aRow = tid >> 1, aCol = (tid & 1) * 4;

    float acc[8][8];
#pragma unroll
    for (int i = 0; i < 8; i++)
#pragma unroll
        for (int j = 0; j < 8; j++) acc[i][j] = 0.f;

    for (int k0 = 0; k0 < HD; k0 += 8) {
        float4 qv = *(const float4*)(Qb + (size_t)aRow * QKVN + k0 + aCol);
        Qs[aCol + 0][aRow] = qv.x; Qs[aCol + 1][aRow] = qv.y;
        Qs[aCol + 2][aRow] = qv.z; Qs[aCol + 3][aRow] = qv.w;
        float4 kv = *(const float4*)(Kb + (size_t)aRow * QKVN + k0 + aCol);
        Ks[aCol + 0][aRow] = kv.x; Ks[aCol + 1][aRow] = kv.y;
        Ks[aCol + 2][aRow] = kv.z; Ks[aCol + 3][aRow] = kv.w;
        __syncthreads();
#pragma unroll
        for (int kk = 0; kk < 8; kk++) {
            float qr[8], kr[8];
#pragma unroll
            for (int i = 0; i < 8; i++) qr[i] = Qs[kk][trow * 8 + i];
#pragma unroll
            for (int j = 0; j < 8; j++) kr[j] = Ks[kk][tcol * 8 + j];
#pragma unroll
            for (int i = 0; i < 8; i++)
#pragma unroll
                for (int j = 0; j < 8; j++) acc[i][j] += qr[i] * kr[j];
        }
        __syncthreads();
    }

#pragma unroll
    for (int i = 0; i < 8; i++) {
        const int s = s0 + trow * 8 + i;
#pragma unroll
        for (int j = 0; j < 8; j += 4) {
            const int t = t0 + tcol * 8 + j;
            float4 v;
            v.x = acc[i][j] * scale;     v.y = acc[i][j + 1] * scale;
            v.z = acc[i][j + 2] * scale; v.w = acc[i][j + 3] * scale;
            *(float4*)(Cb + (size_t)s * SEQ + t) = v;
        }
    }
}

// ---------------------------------------------------------------------------
// Causal softmax: one block per (head, s) row. Reads t in [0, s], writes
// probs there and zeros in (s, SEQ).
// grid: NQH*SEQ blocks, 256 threads.
// ---------------------------------------------------------------------------
__global__ __launch_bounds__(256) void softmax_causal()
{
    const int row = blockIdx.x;            // h*SEQ + s
    const int s   = row & (SEQ - 1);
    const int len = s + 1;
    float* p = g_scores + (size_t)row * SEQ;
    const int tid = threadIdx.x;

    __shared__ float red[8];

    float m = -1e30f;
    for (int i = tid; i < len; i += 256) m = fmaxf(m, p[i]);
#pragma unroll
    for (int o = 16; o; o >>= 1) m = fmaxf(m, __shfl_xor_sync(0xffffffffu, m, o));
    if ((tid & 31) == 0) red[tid >> 5] = m;
    __syncthreads();
    m = red[0];
#pragma unroll
    for (int i = 1; i < 8; i++) m = fmaxf(m, red[i]);

    float sum = 0.f;
    for (int i = tid; i < len; i += 256) {
        float e = __expf(p[i] - m);
        p[i] = e;
        sum += e;
    }
#pragma unroll
    for (int o = 16; o; o >>= 1) sum += __shfl_xor_sync(0xffffffffu, sum, o);
    __syncthreads();
    if ((tid & 31) == 0) red[tid >> 5] = sum;
    __syncthreads();
    sum = 0.f;
#pragma unroll
    for (int i = 0; i < 8; i++) sum += red[i];

    const float inv = 1.0f / sum;
    for (int i = tid; i < len; i += 256) p[i] *= inv;
    for (int i = len + tid; i < SEQ; i += 256) p[i] = 0.f;
}

// ---------------------------------------------------------------------------
// PV: attn[s, h*128 + d] = sum_t P[h,s,t] * V[t, kv(h), d]
// NN GEMM per head: M=2048, N=128, K=2048.  grid: (1, 16, 32)
// ---------------------------------------------------------------------------
__global__ __launch_bounds__(256) void pv_gemm()
{
    const int h = blockIdx.z;
    const float* A = g_scores + (size_t)h * SEQ * SEQ;          // lda = SEQ
    const float* B = g_qkv + HID + KVD + (h >> 2) * HD;          // ldb = QKVN
    float* C = g_attn + h * HD;                                  // ldc = HID

    __shared__ float As[8][128];
    __shared__ float Bs[8][128];

    const int by = blockIdx.y;
    const int tid = threadIdx.x;
    const int trow = tid >> 4, tcol = tid & 15;
    const int aRow = tid >> 1, aCol = (tid & 1) * 4;
    const int bRow = tid >> 5, bCol = (tid & 31) * 4;

    const float* Ab = A + (size_t)by * 128 * SEQ;

    float acc[8][8];
#pragma unroll
    for (int i = 0; i < 8; i++)
#pragma unroll
        for (int j = 0; j < 8; j++) acc[i][j] = 0.f;

    for (int k0 = 0; k0 < SEQ; k0 += 8) {
        float4 av = *(const float4*)(Ab + (size_t)aRow * SEQ + k0 + aCol);
        As[aCol + 0][aRow] = av.x; As[aCol + 1][aRow] = av.y;
        As[aCol + 2][aRow] = av.z; As[aCol + 3][aRow] = av.w;
        *(float4*)&Bs[bRow][bCol] =
            *(const float4*)(B + (size_t)(k0 + bRow) * QKVN + bCol);
        __syncthreads();
#pragma unroll
        for (int kk = 0; kk < 8; kk++) {
            float ar[8], br[8];
#pragma unroll
            for (int i = 0; i < 8; i++) ar[i] = As[kk][trow * 8 + i];
#pragma unroll
            for (int j = 0; j < 8; j++) br[j] = Bs[kk][tcol * 8 + j];
#pragma unroll
            for (int i = 0; i < 8; i++)
#pragma unroll
                for (int j = 0; j < 8; j++) acc[i][j] += ar[i] * br[j];
        }
        __syncthreads();
    }

#pragma unroll
    for (int i = 0; i < 8; i++) {
        const int row = by * 128 + trow * 8 + i;
#pragma unroll
        for (int j = 0; j < 8; j += 4) {
            const int col = tcol * 8 + j;
            float4 v;
            v.x = acc[i][j];     v.y = acc[i][j + 1];
            v.z = acc[i][j + 2]; v.w = acc[i][j + 3];
            *(float4*)(C + (size_t)row * HID + col) = v;
        }
    }
}

// ---------------------------------------------------------------------------
extern "C" void kernel_launch(void* const* d_in, const int* in_sizes, int n_in,
                              void* d_out, int out_size)
{
    const int*   positions = (const int*)d_in[0];
    const float* hidden    = (const float*)d_in[1];
    const float* Wqkv      = (const float*)d_in[2];
    const float* bqkv      = (const float*)d_in[3];
    const float* Wproj     = (const float*)d_in[4];
    const float* bproj     = (const float*)d_in[5];
    float* out = (float*)d_out;

    float *qkv_p, *attn_p;
    cudaGetSymbolAddress((void**)&qkv_p, g_qkv);
    cudaGetSymbolAddress((void**)&attn_p, g_attn);

    // 1) QKV projection: [2048,4096] @ [4096,6144] + bias
    {
        dim3 grid(QKVN / 128, SEQ / 128, 1);
        sgemm_nn_bias<<<grid, 256>>>(SEQ, QKVN, HID,
                                     hidden, HID, Wqkv, QKVN, bqkv,
                                     qkv_p, QKVN);
    }

    // 2) RoPE on Q and K
    {
        const int total = SEQ * 40 * 64;
        rope_kernel<<<(total + 255) / 256, 256>>>(positions);
    }

    // 3) Scores (causal-block-skipped)
    {
        const float scale = 1.0f / sqrtf((float)HD);
        dim3 grid(SEQ / 128, SEQ / 128, NQH);
        scores_nt<<<grid, 256>>>(scale);
    }

    // 4) Row softmax with causal length
    softmax_causal<<<NQH * SEQ, 256>>>();

    // 5) P @ V
    {
        dim3 grid(1, SEQ / 128, NQH);
        pv_gemm<<<grid, 256>>>();
    }

    // 6) Output projection: [2048,4096] @ [4096,4096] + bias
    {
        dim3 grid(HID / 128, SEQ / 128, 1);
        sgemm_nn_bias<<<grid, 256>>>(SEQ, HID, HID,
                                     attn_p, HID, Wproj, HID, bproj,
                                     out, HID);
    }
}